// round 1
// baseline (speedup 1.0000x reference)
#include <cuda_runtime.h>
#include <cuda_bf16.h>

// Problem constants (fixed by the reference).
#define N_NODES 100000
#define N_EDGES 1600000
#define F 128        // in feats
#define H 128        // hidden

// Scratch (no cudaMalloc allowed): aggregation buffer + degree counters.
__device__ float g_agg[(size_t)N_NODES * F];
__device__ int   g_deg_out[N_NODES];
__device__ int   g_deg_in[N_NODES];

// ---------------------------------------------------------------------------
// K1: degree histograms. 3.2M int reductions to 200K addresses.
// ---------------------------------------------------------------------------
__global__ void deg_kernel(const int* __restrict__ src, const int* __restrict__ dst,
                           int n_edges) {
    int i = blockIdx.x * blockDim.x + threadIdx.x;
    if (i < n_edges) {
        atomicAdd(&g_deg_out[src[i]], 1);   // return unused -> RED
        atomicAdd(&g_deg_in[dst[i]], 1);
    }
}

// ---------------------------------------------------------------------------
// K2: edge aggregation. One warp per edge; 32 edges batched per warp chunk.
//   lane l: float4 slice of the 128-float row.
//   agg[dst] += X[src] * rsqrt(max(deg_out[src],1))
// X and agg are both L2-resident (51MB each).
// ---------------------------------------------------------------------------
__global__ void agg_kernel(const float* __restrict__ X,
                           const int* __restrict__ src,
                           const int* __restrict__ dst,
                           int n_edges) {
    const int lane = threadIdx.x & 31;
    const int warp = (blockIdx.x * blockDim.x + threadIdx.x) >> 5;
    const int base = warp * 32;
    if (base >= n_edges) return;

    int s = 0, d = 0;
    float sc = 0.0f;
    const int e = base + lane;
    if (e < n_edges) {
        s = src[e];                       // coalesced
        d = dst[e];
        sc = rsqrtf(fmaxf((float)g_deg_out[s], 1.0f));
    }
    const int cnt = min(32, n_edges - base);

    #pragma unroll 1
    for (int i = 0; i < cnt; ++i) {
        const int   ss = __shfl_sync(0xffffffffu, s,  i);
        const int   dd = __shfl_sync(0xffffffffu, d,  i);
        const float sf = __shfl_sync(0xffffffffu, sc, i);

        float4 v = reinterpret_cast<const float4*>(X + (size_t)ss * F)[lane];
        v.x *= sf; v.y *= sf; v.z *= sf; v.w *= sf;

        float* p = g_agg + (size_t)dd * F + lane * 4;
        // return values unused -> ptxas emits RED.E.ADD.F32 (no round trip)
        atomicAdd(p + 0, v.x);
        atomicAdd(p + 1, v.y);
        atomicAdd(p + 2, v.z);
        atomicAdd(p + 3, v.w);
    }
}

// ---------------------------------------------------------------------------
// K3: fused epilogue GEMM.
//   out = relu( (agg * rsqrt(max(deg_in,1))) @ W + bias )
// W (128x128 f32 = 64KB) and a 64-row A tile (32KB) live in dynamic smem.
// 256 threads: thread = (colgroup cg in [0,32) x rowgroup rg in [0,8)).
// Each thread: 8 rows x 4 cols register micro-tile.
// ---------------------------------------------------------------------------
#define TILE_R 64
__global__ void gemm_kernel(const float* __restrict__ W,
                            const float* __restrict__ bias,
                            float* __restrict__ out) {
    extern __shared__ float smem[];
    float* Ws = smem;              // [128][128]
    float* As = smem + 128 * 128;  // [TILE_R][128]

    const int tid  = threadIdx.x;     // 256 threads
    const int row0 = blockIdx.x * TILE_R;

    // Load W (16384 floats) -> smem, float4, fully coalesced.
    for (int i = tid; i < 128 * 128 / 4; i += 256) {
        reinterpret_cast<float4*>(Ws)[i] = reinterpret_cast<const float4*>(W)[i];
    }
    // Load + scale A tile.
    for (int i = tid; i < TILE_R * 128 / 4; i += 256) {
        const int r   = i >> 5;     // 32 float4 per row
        const int c   = i & 31;
        const int row = row0 + r;
        float4 v = make_float4(0.f, 0.f, 0.f, 0.f);
        if (row < N_NODES) {
            v = reinterpret_cast<const float4*>(g_agg + (size_t)row * F)[c];
            const float scn = rsqrtf(fmaxf((float)g_deg_in[row], 1.0f));
            v.x *= scn; v.y *= scn; v.z *= scn; v.w *= scn;
        }
        reinterpret_cast<float4*>(As)[i] = v;
    }
    __syncthreads();

    const int cg = tid & 31;   // cols [4*cg, 4*cg+4)
    const int rg = tid >> 5;   // rows rg*8 .. rg*8+7

    float acc[8][4];
    #pragma unroll
    for (int j = 0; j < 8; ++j)
        #pragma unroll
        for (int c = 0; c < 4; ++c) acc[j][c] = 0.0f;

    #pragma unroll 4
    for (int k = 0; k < 128; ++k) {
        const float4 w4 = reinterpret_cast<const float4*>(Ws + k * 128)[cg];
        #pragma unroll
        for (int j = 0; j < 8; ++j) {
            const float a = As[(rg * 8 + j) * 128 + k];  // warp-broadcast
            acc[j][0] += a * w4.x;
            acc[j][1] += a * w4.y;
            acc[j][2] += a * w4.z;
            acc[j][3] += a * w4.w;
        }
    }

    const float4 b4 = reinterpret_cast<const float4*>(bias)[cg];
    #pragma unroll
    for (int j = 0; j < 8; ++j) {
        const int row = row0 + rg * 8 + j;
        if (row < N_NODES) {
            float4 o;
            o.x = fmaxf(acc[j][0] + b4.x, 0.0f);
            o.y = fmaxf(acc[j][1] + b4.y, 0.0f);
            o.z = fmaxf(acc[j][2] + b4.z, 0.0f);
            o.w = fmaxf(acc[j][3] + b4.w, 0.0f);
            reinterpret_cast<float4*>(out + (size_t)row * H)[cg] = o;
        }
    }
}

// ---------------------------------------------------------------------------
// launch
// ---------------------------------------------------------------------------
extern "C" void kernel_launch(void* const* d_in, const int* in_sizes, int n_in,
                              void* d_out, int out_size) {
    const float* X    = (const float*)d_in[0];   // [N_NODES, F]
    const int*   src  = (const int*)d_in[1];     // [N_EDGES]
    const int*   dst  = (const int*)d_in[2];     // [N_EDGES]
    const float* W    = (const float*)d_in[3];   // [F, H]
    const float* bias = (const float*)d_in[4];   // [H]
    float*       out  = (float*)d_out;           // [N_NODES, H]

    const int n_edges = in_sizes[1];

    // Scratch addresses (not an allocation; symbols live in the module).
    void *agg_ptr = nullptr, *dgo_ptr = nullptr, *dgi_ptr = nullptr;
    cudaGetSymbolAddress(&agg_ptr, g_agg);
    cudaGetSymbolAddress(&dgo_ptr, g_deg_out);
    cudaGetSymbolAddress(&dgi_ptr, g_deg_in);

    // Zero scratch each call (graph replays must be deterministic).
    cudaMemsetAsync(agg_ptr, 0, sizeof(float) * (size_t)N_NODES * F, 0);
    cudaMemsetAsync(dgo_ptr, 0, sizeof(int) * N_NODES, 0);
    cudaMemsetAsync(dgi_ptr, 0, sizeof(int) * N_NODES, 0);

    // K1: degrees
    {
        const int threads = 256;
        const int blocks  = (n_edges + threads - 1) / threads;
        deg_kernel<<<blocks, threads>>>(src, dst, n_edges);
    }

    // K2: edge aggregation (one warp per edge, chunks of 32 edges per warp)
    {
        const int threads    = 256;
        const int warps_need = (n_edges + 31) / 32;
        const int blocks     = (warps_need * 32 + threads - 1) / threads;
        agg_kernel<<<blocks, threads>>>(X, src, dst, n_edges);
    }

    // K3: scaled GEMM + bias + relu
    {
        const int smem_bytes = (128 * 128 + TILE_R * 128) * (int)sizeof(float); // 96KB
        cudaFuncSetAttribute(gemm_kernel,
                             cudaFuncAttributeMaxDynamicSharedMemorySize, smem_bytes);
        const int blocks = (N_NODES + TILE_R - 1) / TILE_R;
        gemm_kernel<<<blocks, 256, smem_bytes>>>(W, bias, out);
    }
}

// round 2
// speedup vs baseline: 1.8540x; 1.8540x over previous
#include <cuda_runtime.h>
#include <cuda_bf16.h>

// Problem constants (fixed by the reference).
#define N_NODES 100000
#define N_EDGES 1600000
#define F 128        // in feats
#define H 128        // hidden

// Scratch (no cudaMalloc allowed).
__device__ float g_agg[(size_t)N_NODES * F];
__device__ int   g_deg_out[N_NODES];
__device__ int   g_deg_in[N_NODES];
__device__ float g_rs_out[N_NODES];   // rsqrt(max(deg_out,1))
__device__ float g_rs_in[N_NODES];    // rsqrt(max(deg_in,1))

// ---------------------------------------------------------------------------
// K1: degree histograms. 4 edges per thread, int4 loads.
// ---------------------------------------------------------------------------
__global__ void deg_kernel(const int* __restrict__ src, const int* __restrict__ dst,
                           int n_edges) {
    int i4 = blockIdx.x * blockDim.x + threadIdx.x;
    int base = i4 * 4;
    if (base + 3 < n_edges) {
        int4 s = reinterpret_cast<const int4*>(src)[i4];
        int4 d = reinterpret_cast<const int4*>(dst)[i4];
        atomicAdd(&g_deg_out[s.x], 1); atomicAdd(&g_deg_out[s.y], 1);
        atomicAdd(&g_deg_out[s.z], 1); atomicAdd(&g_deg_out[s.w], 1);
        atomicAdd(&g_deg_in[d.x], 1);  atomicAdd(&g_deg_in[d.y], 1);
        atomicAdd(&g_deg_in[d.z], 1);  atomicAdd(&g_deg_in[d.w], 1);
    } else {
        for (int e = base; e < n_edges; ++e) {
            atomicAdd(&g_deg_out[src[e]], 1);
            atomicAdd(&g_deg_in[dst[e]], 1);
        }
    }
}

// ---------------------------------------------------------------------------
// K1b: precompute rsqrt scale arrays (removes MUFU/I2F from hot loops).
// ---------------------------------------------------------------------------
__global__ void rsqrt_kernel(int n) {
    int i = blockIdx.x * blockDim.x + threadIdx.x;
    if (i < n) {
        g_rs_out[i] = rsqrtf(fmaxf((float)g_deg_out[i], 1.0f));
        g_rs_in[i]  = rsqrtf(fmaxf((float)g_deg_in[i], 1.0f));
    }
}

// ---------------------------------------------------------------------------
// K2: edge aggregation. One warp per 32-edge chunk; lane = float4 slice.
//   agg[dst] += X[src] * rs_out[src]     (vector RED.128 per lane)
// ---------------------------------------------------------------------------
__global__ void agg_kernel(const float* __restrict__ X,
                           const int* __restrict__ src,
                           const int* __restrict__ dst,
                           int n_edges) {
    const int lane = threadIdx.x & 31;
    const int warp = (blockIdx.x * blockDim.x + threadIdx.x) >> 5;
    const int base = warp * 32;
    if (base >= n_edges) return;

    int s = 0, d = 0;
    float sc = 0.0f;
    const int e = base + lane;
    if (e < n_edges) {
        s = src[e];                 // coalesced
        d = dst[e];
        sc = g_rs_out[s];           // random, L2-resident (400KB)
    }
    const int cnt = min(32, n_edges - base);

    #pragma unroll 1
    for (int i = 0; i < cnt; ++i) {
        const int   ss = __shfl_sync(0xffffffffu, s,  i);
        const int   dd = __shfl_sync(0xffffffffu, d,  i);
        const float sf = __shfl_sync(0xffffffffu, sc, i);

        float4 v = reinterpret_cast<const float4*>(X + (size_t)ss * F)[lane];
        v.x *= sf; v.y *= sf; v.z *= sf; v.w *= sf;

        float4* p = reinterpret_cast<float4*>(g_agg + (size_t)dd * F) + lane;
        atomicAdd(p, v);            // cc9.0+ vector atomic; return unused -> RED.128
    }
}

// ---------------------------------------------------------------------------
// K3: fused epilogue GEMM with f32x2 packed FMA.
//   out = relu( (agg * rs_in) @ W + bias )
// smem: Ws [128][128] f32 (64KB) + As_dup [64][128] f32x2 duplicated (64KB).
// 256 threads; thread = (rg in [0,8)) x (cg in [0,32)); 8 rows x 4 cols each.
// ---------------------------------------------------------------------------
#define TILE_R 64

#define FMA_F32X2(d, a, b, c) \
    asm("fma.rn.f32x2 %0, %1, %2, %3;" : "=l"(d) : "l"(a), "l"(b), "l"(c))
#define PACK_F32X2(out, lo, hi) \
    asm("mov.b64 %0, {%1, %2};" : "=l"(out) : "f"(lo), "f"(hi))
#define UNPACK_F32X2(lo, hi, in) \
    asm("mov.b64 {%0, %1}, %2;" : "=f"(lo), "=f"(hi) : "l"(in))

__global__ void gemm_kernel(const float* __restrict__ Wm,
                            const float* __restrict__ bias,
                            float* __restrict__ out) {
    extern __shared__ float smem[];
    float*  Ws  = smem;                                   // [128][128]
    float2* As2 = reinterpret_cast<float2*>(smem + 128 * 128); // [64][128] dup

    const int tid  = threadIdx.x;     // 256
    const int row0 = blockIdx.x * TILE_R;

    // Load W -> smem (float4, coalesced).
    for (int i = tid; i < 128 * 128 / 4; i += 256)
        reinterpret_cast<float4*>(Ws)[i] = reinterpret_cast<const float4*>(Wm)[i];

    // Load + scale A tile, store DUPLICATED ({a,a}) for direct LDS.64 f32x2 use.
    for (int i = tid; i < TILE_R * 128 / 4; i += 256) {
        const int r   = i >> 5;          // 32 float4 per row
        const int c   = i & 31;
        const int row = row0 + r;
        float4 v = make_float4(0.f, 0.f, 0.f, 0.f);
        if (row < N_NODES) {
            v = reinterpret_cast<const float4*>(g_agg + (size_t)row * F)[c];
            const float scn = g_rs_in[row];
            v.x *= scn; v.y *= scn; v.z *= scn; v.w *= scn;
        }
        float2* dstp = As2 + r * 128 + c * 4;
        dstp[0] = make_float2(v.x, v.x);
        dstp[1] = make_float2(v.y, v.y);
        dstp[2] = make_float2(v.z, v.z);
        dstp[3] = make_float2(v.w, v.w);
    }
    __syncthreads();

    const int cg = tid & 31;   // cols [4*cg, 4*cg+4)
    const int rg = tid >> 5;   // rows rg*8 .. rg*8+7

    unsigned long long acc[8][2];
    #pragma unroll
    for (int j = 0; j < 8; ++j) { acc[j][0] = 0ull; acc[j][1] = 0ull; }

    const unsigned long long* Arow =
        reinterpret_cast<const unsigned long long*>(As2 + (rg * 8) * 128);

    #pragma unroll 8
    for (int k = 0; k < 128; ++k) {
        const float4 w4 = reinterpret_cast<const float4*>(Ws + k * 128)[cg];
        unsigned long long w01, w23;
        PACK_F32X2(w01, w4.x, w4.y);   // register-pair alias, usually free
        PACK_F32X2(w23, w4.z, w4.w);
        #pragma unroll
        for (int j = 0; j < 8; ++j) {
            const unsigned long long aa = Arow[j * 128 + k];  // LDS.64 broadcast {a,a}
            FMA_F32X2(acc[j][0], aa, w01, acc[j][0]);
            FMA_F32X2(acc[j][1], aa, w23, acc[j][1]);
        }
    }

    const float4 b4 = reinterpret_cast<const float4*>(bias)[cg];
    #pragma unroll
    for (int j = 0; j < 8; ++j) {
        const int row = row0 + rg * 8 + j;
        if (row < N_NODES) {
            float c0, c1, c2, c3;
            UNPACK_F32X2(c0, c1, acc[j][0]);
            UNPACK_F32X2(c2, c3, acc[j][1]);
            float4 o;
            o.x = fmaxf(c0 + b4.x, 0.0f);
            o.y = fmaxf(c1 + b4.y, 0.0f);
            o.z = fmaxf(c2 + b4.z, 0.0f);
            o.w = fmaxf(c3 + b4.w, 0.0f);
            reinterpret_cast<float4*>(out + (size_t)row * H)[cg] = o;
        }
    }
}

// ---------------------------------------------------------------------------
// launch
// ---------------------------------------------------------------------------
extern "C" void kernel_launch(void* const* d_in, const int* in_sizes, int n_in,
                              void* d_out, int out_size) {
    const float* X    = (const float*)d_in[0];   // [N_NODES, F]
    const int*   src  = (const int*)d_in[1];     // [N_EDGES]
    const int*   dst  = (const int*)d_in[2];     // [N_EDGES]
    const float* Wm   = (const float*)d_in[3];   // [F, H]
    const float* bias = (const float*)d_in[4];   // [H]
    float*       out  = (float*)d_out;           // [N_NODES, H]

    const int n_edges = in_sizes[1];

    void *agg_ptr = nullptr, *dgo_ptr = nullptr, *dgi_ptr = nullptr;
    cudaGetSymbolAddress(&agg_ptr, g_agg);
    cudaGetSymbolAddress(&dgo_ptr, g_deg_out);
    cudaGetSymbolAddress(&dgi_ptr, g_deg_in);

    cudaMemsetAsync(agg_ptr, 0, sizeof(float) * (size_t)N_NODES * F, 0);
    cudaMemsetAsync(dgo_ptr, 0, sizeof(int) * N_NODES, 0);
    cudaMemsetAsync(dgi_ptr, 0, sizeof(int) * N_NODES, 0);

    // K1: degrees (4 edges/thread)
    {
        const int threads = 256;
        const int blocks  = (n_edges / 4 + threads - 1) / threads + 1;
        deg_kernel<<<blocks, threads>>>(src, dst, n_edges);
    }
    // K1b: rsqrt scales
    {
        const int threads = 256;
        const int blocks  = (N_NODES + threads - 1) / threads;
        rsqrt_kernel<<<blocks, threads>>>(N_NODES);
    }
    // K2: edge aggregation
    {
        const int threads    = 256;
        const int warps_need = (n_edges + 31) / 32;
        const int blocks     = (warps_need + 7) / 8;
        agg_kernel<<<blocks, threads>>>(X, src, dst, n_edges);
    }
    // K3: scaled GEMM + bias + relu
    {
        const int smem_bytes = 128 * 1024;   // 64KB W + 64KB duplicated A
        cudaFuncSetAttribute(gemm_kernel,
                             cudaFuncAttributeMaxDynamicSharedMemorySize, smem_bytes);
        const int blocks = (N_NODES + TILE_R - 1) / TILE_R;
        gemm_kernel<<<blocks, 256, smem_bytes>>>(Wm, bias, out);
    }
}

// round 4
// speedup vs baseline: 2.0934x; 1.1291x over previous
#include <cuda_runtime.h>
#include <cuda_bf16.h>

#define N_NODES 100000
#define N_EDGES 1600000
#define F 128
#define H 128
#define NB_SCAN ((N_NODES + 255) / 256)   // 391

// Scratch (__device__ globals; no cudaMalloc allowed).
__device__ float g_agg[(size_t)N_NODES * F];   // normalized aggregation (rs_in folded in)
__device__ int   g_deg_out[N_NODES];
__device__ int   g_deg_in[N_NODES];
__device__ float g_rs_out[N_NODES];
__device__ float g_rs_in[N_NODES];
__device__ int   g_esrc[N_EDGES];              // src ids sorted by dst
__device__ int   g_rowtmp[N_NODES];            // per-block exclusive prefix
__device__ int   g_blksum[512];
__device__ int   g_blkoff[512];
__device__ int   g_row_start[N_NODES];
__device__ int   g_cursor[N_NODES];

// ---------------------------------------------------------------------------
// K1: degree histograms (4 edges/thread, int4 loads).
// ---------------------------------------------------------------------------
__global__ void deg_kernel(const int* __restrict__ src, const int* __restrict__ dst,
                           int n_edges) {
    int i4 = blockIdx.x * blockDim.x + threadIdx.x;
    int base = i4 * 4;
    if (base + 3 < n_edges) {
        int4 s = reinterpret_cast<const int4*>(src)[i4];
        int4 d = reinterpret_cast<const int4*>(dst)[i4];
        atomicAdd(&g_deg_out[s.x], 1); atomicAdd(&g_deg_out[s.y], 1);
        atomicAdd(&g_deg_out[s.z], 1); atomicAdd(&g_deg_out[s.w], 1);
        atomicAdd(&g_deg_in[d.x], 1);  atomicAdd(&g_deg_in[d.y], 1);
        atomicAdd(&g_deg_in[d.z], 1);  atomicAdd(&g_deg_in[d.w], 1);
    } else {
        for (int e = base; e < n_edges; ++e) {
            atomicAdd(&g_deg_out[src[e]], 1);
            atomicAdd(&g_deg_in[dst[e]], 1);
        }
    }
}

// ---------------------------------------------------------------------------
// K1b: rsqrt scale arrays.
// ---------------------------------------------------------------------------
__global__ void rsqrt_kernel() {
    int i = blockIdx.x * blockDim.x + threadIdx.x;
    if (i < N_NODES) {
        g_rs_out[i] = rsqrtf(fmaxf((float)g_deg_out[i], 1.0f));
        g_rs_in[i]  = rsqrtf(fmaxf((float)g_deg_in[i], 1.0f));
    }
}

// ---------------------------------------------------------------------------
// Scan (3 kernels): exclusive prefix sum of deg_in -> row_start, cursor.
// ---------------------------------------------------------------------------
__global__ void scan_block_kernel() {
    __shared__ int sm[256];
    const int tid = threadIdx.x;
    const int i = blockIdx.x * 256 + tid;
    int v = (i < N_NODES) ? g_deg_in[i] : 0;
    sm[tid] = v;
    __syncthreads();
    #pragma unroll
    for (int off = 1; off < 256; off <<= 1) {
        int t = (tid >= off) ? sm[tid - off] : 0;
        __syncthreads();
        sm[tid] += t;
        __syncthreads();
    }
    if (i < N_NODES) g_rowtmp[i] = sm[tid] - v;       // exclusive within block
    if (tid == 255) g_blksum[blockIdx.x] = sm[255];
}

__global__ void scan_top_kernel() {
    __shared__ int sm[512];
    const int tid = threadIdx.x;  // 512
    int v = (tid < NB_SCAN) ? g_blksum[tid] : 0;
    sm[tid] = v;
    __syncthreads();
    #pragma unroll
    for (int off = 1; off < 512; off <<= 1) {
        int t = (tid >= off) ? sm[tid - off] : 0;
        __syncthreads();
        sm[tid] += t;
        __syncthreads();
    }
    g_blkoff[tid] = sm[tid] - v;                       // exclusive
}

__global__ void scan_add_kernel() {
    int i = blockIdx.x * blockDim.x + threadIdx.x;
    if (i < N_NODES) {
        int base = g_rowtmp[i] + g_blkoff[i >> 8];
        g_row_start[i] = base;
        g_cursor[i]    = base;
    }
}

// ---------------------------------------------------------------------------
// Scatter: counting-sort src ids by dst (4 edges/thread, int4 loads).
// ---------------------------------------------------------------------------
__global__ void scatter_kernel(const int* __restrict__ src, const int* __restrict__ dst,
                               int n_edges) {
    int i4 = blockIdx.x * blockDim.x + threadIdx.x;
    int base = i4 * 4;
    if (base + 3 < n_edges) {
        int4 s = reinterpret_cast<const int4*>(src)[i4];
        int4 d = reinterpret_cast<const int4*>(dst)[i4];
        g_esrc[atomicAdd(&g_cursor[d.x], 1)] = s.x;
        g_esrc[atomicAdd(&g_cursor[d.y], 1)] = s.y;
        g_esrc[atomicAdd(&g_cursor[d.z], 1)] = s.z;
        g_esrc[atomicAdd(&g_cursor[d.w], 1)] = s.w;
    } else {
        for (int e = base; e < n_edges; ++e)
            g_esrc[atomicAdd(&g_cursor[dst[e]], 1)] = src[e];
    }
}

// ---------------------------------------------------------------------------
// K2: CSR aggregation. One warp per dst node; lane = float4 slice of the row.
//   g_agg[d] = rs_in[d] * sum_{s in N(d)} X[s] * rs_out[s]      (plain STG)
// ---------------------------------------------------------------------------
__global__ void agg_csr_kernel(const float* __restrict__ X) {
    const int warp = (blockIdx.x * blockDim.x + threadIdx.x) >> 5;
    if (warp >= N_NODES) return;
    const int lane  = threadIdx.x & 31;
    const int start = g_row_start[warp];
    const int n     = g_deg_in[warp];

    float4 acc = make_float4(0.f, 0.f, 0.f, 0.f);
    for (int b = 0; b < n; b += 32) {
        const int rem = n - b;
        int s = 0; float sc = 0.0f;
        if (lane < rem) {
            s  = g_esrc[start + b + lane];   // coalesced
            sc = g_rs_out[s];                // random, L2-resident (400KB)
        }
        const int m = min(rem, 32);
        #pragma unroll 1
        for (int i = 0; i < m; ++i) {
            const int   ss = __shfl_sync(0xffffffffu, s,  i);
            const float sf = __shfl_sync(0xffffffffu, sc, i);
            float4 v = reinterpret_cast<const float4*>(X + (size_t)ss * F)[lane];
            acc.x += v.x * sf; acc.y += v.y * sf;
            acc.z += v.z * sf; acc.w += v.w * sf;
        }
    }
    const float ri = g_rs_in[warp];
    acc.x *= ri; acc.y *= ri; acc.z *= ri; acc.w *= ri;
    reinterpret_cast<float4*>(g_agg + (size_t)warp * F)[lane] = acc;
}

// ---------------------------------------------------------------------------
// K3: GEMM + bias + relu. 128x128 tile/block, 8x8 micro-tile, f32x2 FMA.
// smem: Ws [128][128] f32 (64KB) + As2 [128][128] float2 dup (128KB) = 192KB.
// 256 threads: cg = tid&15 -> cols [8cg,8cg+8); rg = tid>>4 -> rows [8rg,8rg+8).
// ---------------------------------------------------------------------------
#define FMA_F32X2(d, a, b) \
    asm("fma.rn.f32x2 %0, %1, %2, %0;" : "+l"(d) : "l"(a), "l"(b))
#define UNPACK_F32X2(lo, hi, in) \
    asm("mov.b64 {%0, %1}, %2;" : "=f"(lo), "=f"(hi) : "l"(in))

__global__ void __launch_bounds__(256, 1)
gemm_kernel(const float* __restrict__ Wm,
            const float* __restrict__ bias,
            float* __restrict__ out) {
    extern __shared__ float smem[];
    float*  Ws  = smem;                                        // [128][128]
    float2* As2 = reinterpret_cast<float2*>(smem + 128 * 128); // [128][128] dup

    const int tid  = threadIdx.x;
    const int row0 = blockIdx.x * 128;

    // Stage W (64KB, coalesced float4).
    for (int i = tid; i < 128 * 32; i += 256)
        reinterpret_cast<float4*>(Ws)[i] = reinterpret_cast<const float4*>(Wm)[i];

    // Stage A tile duplicated {a,a}.
    for (int i = tid; i < 128 * 32; i += 256) {
        const int r   = i >> 5;
        const int c   = i & 31;
        const int row = row0 + r;
        float4 v = make_float4(0.f, 0.f, 0.f, 0.f);
        if (row < N_NODES)
            v = reinterpret_cast<const float4*>(g_agg + (size_t)row * F)[c];
        float2* dp = As2 + r * 128 + c * 4;
        dp[0] = make_float2(v.x, v.x);
        dp[1] = make_float2(v.y, v.y);
        dp[2] = make_float2(v.z, v.z);
        dp[3] = make_float2(v.w, v.w);
    }
    __syncthreads();

    const int cg = tid & 15;    // cols [8cg, 8cg+8)
    const int rg = tid >> 4;    // rows [8rg, 8rg+8)

    unsigned long long acc[8][4];
    #pragma unroll
    for (int j = 0; j < 8; ++j)
        #pragma unroll
        for (int c = 0; c < 4; ++c) acc[j][c] = 0ull;

    const float* wbase = Ws + cg * 8;
    const float2* abase = As2 + (rg * 8) * 128;

    #pragma unroll 4
    for (int k = 0; k < 128; k += 2) {
        // w[k][8cg..8cg+8) and w[k+1][...] as f32x2 pairs (adjacent floats).
        const ulonglong2 wA = *reinterpret_cast<const ulonglong2*>(wbase + k * 128);
        const ulonglong2 wB = *reinterpret_cast<const ulonglong2*>(wbase + k * 128 + 4);
        const ulonglong2 wC = *reinterpret_cast<const ulonglong2*>(wbase + (k + 1) * 128);
        const ulonglong2 wD = *reinterpret_cast<const ulonglong2*>(wbase + (k + 1) * 128 + 4);
        #pragma unroll
        for (int j = 0; j < 8; ++j) {
            // {a_k,a_k},{a_{k+1},a_{k+1}} in one LDS.128 (broadcast within rg).
            const ulonglong2 aa =
                *reinterpret_cast<const ulonglong2*>(abase + j * 128 + k);
            FMA_F32X2(acc[j][0], aa.x, wA.x);
            FMA_F32X2(acc[j][1], aa.x, wA.y);
            FMA_F32X2(acc[j][2], aa.x, wB.x);
            FMA_F32X2(acc[j][3], aa.x, wB.y);
            FMA_F32X2(acc[j][0], aa.y, wC.x);
            FMA_F32X2(acc[j][1], aa.y, wC.y);
            FMA_F32X2(acc[j][2], aa.y, wD.x);
            FMA_F32X2(acc[j][3], aa.y, wD.y);
        }
    }

    const float4 b0 = reinterpret_cast<const float4*>(bias)[cg * 2];
    const float4 b1 = reinterpret_cast<const float4*>(bias)[cg * 2 + 1];
    #pragma unroll
    for (int j = 0; j < 8; ++j) {
        const int row = row0 + rg * 8 + j;
        if (row < N_NODES) {
            float c0, c1, c2, c3, c4, c5, c6, c7;
            UNPACK_F32X2(c0, c1, acc[j][0]);
            UNPACK_F32X2(c2, c3, acc[j][1]);
            UNPACK_F32X2(c4, c5, acc[j][2]);
            UNPACK_F32X2(c6, c7, acc[j][3]);
            float4 o0, o1;
            o0.x = fmaxf(c0 + b0.x, 0.f); o0.y = fmaxf(c1 + b0.y, 0.f);
            o0.z = fmaxf(c2 + b0.z, 0.f); o0.w = fmaxf(c3 + b0.w, 0.f);
            o1.x = fmaxf(c4 + b1.x, 0.f); o1.y = fmaxf(c5 + b1.y, 0.f);
            o1.z = fmaxf(c6 + b1.z, 0.f); o1.w = fmaxf(c7 + b1.w, 0.f);
            float4* op = reinterpret_cast<float4*>(out + (size_t)row * H) + cg * 2;
            op[0] = o0;
            op[1] = o1;
        }
    }
}

// ---------------------------------------------------------------------------
// launch
// ---------------------------------------------------------------------------
extern "C" void kernel_launch(void* const* d_in, const int* in_sizes, int n_in,
                              void* d_out, int out_size) {
    const float* X    = (const float*)d_in[0];
    const int*   src  = (const int*)d_in[1];
    const int*   dst  = (const int*)d_in[2];
    const float* Wm   = (const float*)d_in[3];
    const float* bias = (const float*)d_in[4];
    float*       out  = (float*)d_out;

    const int n_edges = in_sizes[1];

    void *dgo = nullptr, *dgi = nullptr;
    cudaGetSymbolAddress(&dgo, g_deg_out);
    cudaGetSymbolAddress(&dgi, g_deg_in);
    cudaMemsetAsync(dgo, 0, sizeof(int) * N_NODES, 0);
    cudaMemsetAsync(dgi, 0, sizeof(int) * N_NODES, 0);

    // degrees
    deg_kernel<<<(n_edges / 4 + 255) / 256 + 1, 256>>>(src, dst, n_edges);
    // rsqrt scales
    rsqrt_kernel<<<(N_NODES + 255) / 256, 256>>>();
    // exclusive scan of deg_in
    scan_block_kernel<<<NB_SCAN, 256>>>();
    scan_top_kernel<<<1, 512>>>();
    scan_add_kernel<<<(N_NODES + 255) / 256, 256>>>();
    // counting sort by dst
    scatter_kernel<<<(n_edges / 4 + 255) / 256 + 1, 256>>>(src, dst, n_edges);
    // CSR aggregation (warp per node)
    agg_csr_kernel<<<(N_NODES * 32 + 255) / 256, 256>>>(X);
    // GEMM + bias + relu
    {
        const int smem_bytes = (128 * 128 + 2 * 128 * 128) * (int)sizeof(float); // 192KB
        cudaFuncSetAttribute(gemm_kernel,
                             cudaFuncAttributeMaxDynamicSharedMemorySize, smem_bytes);
        gemm_kernel<<<(N_NODES + 127) / 128, 256, smem_bytes>>>(Wm, bias, out);
    }
}